// round 3
// baseline (speedup 1.0000x reference)
#include <cuda_runtime.h>

#define NE 16
#define NK 4
#define NH 2048
#define NF 4096
#define NT 64
#define JA 24
#define JB 24

typedef unsigned long long u64;

__device__ float g_act[(size_t)NE * NT * NF];   // 16.8 MB scratch
__device__ int   g_cnt[NE];
__device__ int   g_tok[NE * NT];
__device__ float g_rw [NE * NT];

__device__ __forceinline__ u64 pk2(float lo, float hi) {
    u64 r; asm("mov.b64 %0,{%1,%2};" : "=l"(r) : "f"(lo), "f"(hi)); return r;
}
__device__ __forceinline__ void upk2(u64 v, float &lo, float &hi) {
    asm("mov.b64 {%0,%1},%2;" : "=f"(lo), "=f"(hi) : "l"(v));
}
__device__ __forceinline__ void fma2(u64 &d, u64 a, u64 b) {
    asm("fma.rn.f32x2 %0,%1,%2,%0;" : "+l"(d) : "l"(a), "l"(b));
}
__device__ __forceinline__ u64 add2(u64 a, u64 b) {
    u64 r; asm("add.rn.f32x2 %0,%1,%2;" : "=l"(r) : "l"(a), "l"(b)); return r;
}

// ---------------------------------------------------------------------------
// Setup: zero out + per-expert token lists (duplicate expert ids merged)
// ---------------------------------------------------------------------------
__global__ void setup_kernel(const int* __restrict__ tope,
                             const float* __restrict__ topw,
                             float* __restrict__ out)
{
    int gid = blockIdx.x * blockDim.x + threadIdx.x;
    float4 z = make_float4(0.f, 0.f, 0.f, 0.f);
    float4* o4 = (float4*)out;
    for (int i = gid; i < (NT * NH) / 4; i += gridDim.x * blockDim.x) o4[i] = z;

    if (blockIdx.x == 0 && threadIdx.x < NE) {
        int e = threadIdx.x, c = 0;
        for (int t = 0; t < NT; t++) {
            float r = 0.f; int hit = 0;
#pragma unroll
            for (int k = 0; k < NK; k++)
                if (tope[t * NK + k] == e) { r += topw[t * NK + k]; hit = 1; }
            if (hit) { g_tok[e * NT + c] = t; g_rw[e * NT + c] = r; c++; }
        }
        g_cnt[e] = c;
    }
}

// ---------------------------------------------------------------------------
// Stage A: act[e][j][f] = rw * silu(x_j . w1_f) * (x_j . v1_f)
// Warp handles an (f, f+1) row pair; acc are f32x2 pairs over the two rows.
// ---------------------------------------------------------------------------
template<int JT>
__device__ __forceinline__ void stageA_body(
    const float* __restrict__ w1, const float* __restrict__ v1,
    const float* xs, const float* srw, int e, int fbase, int jbase, int J)
{
    const int tid = threadIdx.x, warp = tid >> 5, lane = tid & 31;
    const float4* xs4 = (const float4*)xs;

#pragma unroll 1
    for (int pass = 0; pass < 4; pass++) {
        const int f0 = fbase + pass * 16 + warp * 2;
        const float4* pw0 = (const float4*)(w1 + ((size_t)e * NF + f0    ) * NH);
        const float4* pw1 = (const float4*)(w1 + ((size_t)e * NF + f0 + 1) * NH);
        const float4* pv0 = (const float4*)(v1 + ((size_t)e * NF + f0    ) * NH);
        const float4* pv1 = (const float4*)(v1 + ((size_t)e * NF + f0 + 1) * NH);

        u64 g[JT], u[JT];
#pragma unroll
        for (int j = 0; j < JT; j++) { g[j] = 0ull; u[j] = 0ull; }

        float4 cw0 = __ldg(pw0 + lane), cw1 = __ldg(pw1 + lane);
        float4 cv0 = __ldg(pv0 + lane), cv1 = __ldg(pv1 + lane);

#pragma unroll 1
        for (int c = 0; c < 16; c++) {
            const int qn = (c < 15) ? ((c + 1) * 32 + lane) : lane;
            const float4 nw0 = __ldg(pw0 + qn), nw1 = __ldg(pw1 + qn);
            const float4 nv0 = __ldg(pv0 + qn), nv1 = __ldg(pv1 + qn);

            const u64 gw0 = pk2(cw0.x, cw1.x), gw1 = pk2(cw0.y, cw1.y);
            const u64 gw2 = pk2(cw0.z, cw1.z), gw3 = pk2(cw0.w, cw1.w);
            const u64 vw0 = pk2(cv0.x, cv1.x), vw1 = pk2(cv0.y, cv1.y);
            const u64 vw2 = pk2(cv0.z, cv1.z), vw3 = pk2(cv0.w, cv1.w);

            const int qb = c * 32 + lane;
#pragma unroll
            for (int j = 0; j < JT; j++) {
                const float4 xv = xs4[j * 512 + qb];
                const u64 x0 = pk2(xv.x, xv.x), x1 = pk2(xv.y, xv.y);
                const u64 x2 = pk2(xv.z, xv.z), x3 = pk2(xv.w, xv.w);
                fma2(g[j], gw0, x0); fma2(u[j], vw0, x0);
                fma2(g[j], gw1, x1); fma2(u[j], vw1, x1);
                fma2(g[j], gw2, x2); fma2(u[j], vw2, x2);
                fma2(g[j], gw3, x3); fma2(u[j], vw3, x3);
            }
            cw0 = nw0; cw1 = nw1; cv0 = nv0; cv1 = nv1;
        }

#pragma unroll
        for (int j = 0; j < JT; j++) {
            u64 gg = g[j], uu = u[j];
#pragma unroll
            for (int o = 16; o; o >>= 1) {
                gg = add2(gg, __shfl_xor_sync(0xffffffffu, gg, o));
                uu = add2(uu, __shfl_xor_sync(0xffffffffu, uu, o));
            }
            if (lane == 0 && j < J) {
                float g0, g1, u0, u1;
                upk2(gg, g0, g1); upk2(uu, u0, u1);
                const float s0 = g0 / (1.f + __expf(-g0));
                const float s1 = g1 / (1.f + __expf(-g1));
                const float r = srw[j];
                float2 o2; o2.x = s0 * u0 * r; o2.y = s1 * u1 * r;
                *(float2*)(g_act + ((size_t)(e * NT + jbase + j)) * NF + f0) = o2;
            }
        }
    }
}

__global__ void __launch_bounds__(256, 1) stageA_kernel(
    const float* __restrict__ x, const float* __restrict__ w1, const float* __restrict__ v1)
{
    const int e = blockIdx.y, jbase = blockIdx.z * JA;
    const int cnt = g_cnt[e];
    if (jbase >= cnt) return;
    const int J  = min(JA, cnt - jbase);
    const int Jp = ((J + 3) >> 2) << 2;

    extern __shared__ float xs[];
    __shared__ int   stok[JA];
    __shared__ float srw [JA];
    const int tid = threadIdx.x;
    if (tid < JA) {
        stok[tid] = (tid < J) ? g_tok[e * NT + jbase + tid] : 0;
        srw [tid] = (tid < J) ? g_rw [e * NT + jbase + tid] : 0.f;
    }
    __syncthreads();

    float4* xs4 = (float4*)xs;
    const float4* x4 = (const float4*)x;
    for (int idx = tid; idx < Jp * 512; idx += 256) {
        const int j = idx >> 9, q = idx & 511;
        xs4[idx] = (j < J) ? __ldg(x4 + (size_t)stok[j] * 512 + q)
                           : make_float4(0.f, 0.f, 0.f, 0.f);
    }
    __syncthreads();

    const int fbase = blockIdx.x * 64;
    switch ((J + 3) >> 2) {
        case 1:  stageA_body<4 >(w1, v1, xs, srw, e, fbase, jbase, J); break;
        case 2:  stageA_body<8 >(w1, v1, xs, srw, e, fbase, jbase, J); break;
        case 3:  stageA_body<12>(w1, v1, xs, srw, e, fbase, jbase, J); break;
        case 4:  stageA_body<16>(w1, v1, xs, srw, e, fbase, jbase, J); break;
        case 5:  stageA_body<20>(w1, v1, xs, srw, e, fbase, jbase, J); break;
        default: stageA_body<24>(w1, v1, xs, srw, e, fbase, jbase, J); break;
    }
}

// ---------------------------------------------------------------------------
// Stage B: out[t] += act[e][j] @ w2_e   (rw already folded into act)
// acc are f32x2 pairs over (f, f+1); act slice staged in smem (broadcast LDS).
// ---------------------------------------------------------------------------
template<int JT>
__device__ __forceinline__ void stageB_body(
    const float* __restrict__ w2, float* __restrict__ out,
    const float* as_, const int* stok, int e, int h0, int f0, int J)
{
    const int tid = threadIdx.x;
    const int h = h0 + tid * 2;
    u64 a0[JT], a1[JT];
#pragma unroll
    for (int j = 0; j < JT; j++) { a0[j] = 0ull; a1[j] = 0ull; }

    const float* wb = w2 + ((size_t)e * NF + f0) * NH + h;
    float2 c0 = __ldg((const float2*)wb);
    float2 c1 = __ldg((const float2*)(wb + NH));

#pragma unroll 1
    for (int p = 0; p < 256; p++) {
        float2 n0 = c0, n1 = c1;
        if (p < 255) {
            const float* nx = wb + (size_t)(2 * p + 2) * NH;
            n0 = __ldg((const float2*)nx);
            n1 = __ldg((const float2*)(nx + NH));
        }
        const u64 wp0 = pk2(c0.x, c1.x);
        const u64 wp1 = pk2(c0.y, c1.y);
#pragma unroll
        for (int j = 0; j < JT; j++) {
            const u64 aj = *(const u64*)(as_ + j * 512 + 2 * p);
            fma2(a0[j], wp0, aj);
            fma2(a1[j], wp1, aj);
        }
        c0 = n0; c1 = n1;
    }

#pragma unroll
    for (int j = 0; j < JT; j++) {
        if (j < J) {
            float l0, r0, l1, r1;
            upk2(a0[j], l0, r0); upk2(a1[j], l1, r1);
            float* op = out + (size_t)stok[j] * NH + h;
            atomicAdd(op,     l0 + r0);
            atomicAdd(op + 1, l1 + r1);
        }
    }
}

__global__ void __launch_bounds__(256, 1) stageB_kernel(
    const float* __restrict__ w2, float* __restrict__ out)
{
    const int e = blockIdx.y;
    const int fs = blockIdx.z & 7, jc = blockIdx.z >> 3;
    const int jbase = jc * JB;
    const int cnt = g_cnt[e];
    if (jbase >= cnt) return;
    const int J  = min(JB, cnt - jbase);
    const int Jp = ((J + 3) >> 2) << 2;
    const int h0 = blockIdx.x * 512, f0 = fs * 512;

    extern __shared__ float as_[];
    __shared__ int stok[JB];
    const int tid = threadIdx.x;
    if (tid < JB) stok[tid] = (tid < J) ? g_tok[e * NT + jbase + tid] : 0;
    __syncthreads();

    float4* a4 = (float4*)as_;
    for (int idx = tid; idx < Jp * 128; idx += 256) {
        const int j = idx >> 7, q = idx & 127;
        a4[idx] = (j < J)
            ? *(const float4*)(g_act + ((size_t)(e * NT + jbase + j)) * NF + f0 + q * 4)
            : make_float4(0.f, 0.f, 0.f, 0.f);
    }
    __syncthreads();

    switch ((J + 3) >> 2) {
        case 1:  stageB_body<4 >(w2, out, as_, stok, e, h0, f0, J); break;
        case 2:  stageB_body<8 >(w2, out, as_, stok, e, h0, f0, J); break;
        case 3:  stageB_body<12>(w2, out, as_, stok, e, h0, f0, J); break;
        case 4:  stageB_body<16>(w2, out, as_, stok, e, h0, f0, J); break;
        case 5:  stageB_body<20>(w2, out, as_, stok, e, h0, f0, J); break;
        default: stageB_body<24>(w2, out, as_, stok, e, h0, f0, J); break;
    }
}

// ---------------------------------------------------------------------------
extern "C" void kernel_launch(void* const* d_in, const int* in_sizes, int n_in,
                              void* d_out, int out_size)
{
    const float* x    = (const float*)d_in[0];
    const float* topw = (const float*)d_in[2];
    const int*   tope = (const int*)  d_in[3];
    const float* w1   = (const float*)d_in[4];
    const float* v1   = (const float*)d_in[5];
    const float* w2   = (const float*)d_in[6];
    float* out = (float*)d_out;

    cudaFuncSetAttribute(stageA_kernel, cudaFuncAttributeMaxDynamicSharedMemorySize, 196608);
    cudaFuncSetAttribute(stageB_kernel, cudaFuncAttributeMaxDynamicSharedMemorySize, 49152);

    setup_kernel<<<64, 256>>>(tope, topw, out);
    stageA_kernel<<<dim3(64, NE, 3),  256, 196608>>>(x, w1, v1);
    stageB_kernel<<<dim3(4,  NE, 24), 256, 49152>>>(w2, out);
}

// round 4
// speedup vs baseline: 1.3344x; 1.3344x over previous
#include <cuda_runtime.h>

#define NE 16
#define NK 4
#define NH 2048
#define NF 4096
#define NT 64
#define JA 16
#define JB 24

typedef unsigned long long u64;

__device__ float g_act[(size_t)NE * NT * NF];   // 16.8 MB scratch
__device__ int   g_cnt[NE];
__device__ int   g_tok[NE * NT];
__device__ float g_rw [NE * NT];

__device__ __forceinline__ u64 pk2(float lo, float hi) {
    u64 r; asm("mov.b64 %0,{%1,%2};" : "=l"(r) : "f"(lo), "f"(hi)); return r;
}
__device__ __forceinline__ void upk2(u64 v, float &lo, float &hi) {
    asm("mov.b64 {%0,%1},%2;" : "=f"(lo), "=f"(hi) : "l"(v));
}
__device__ __forceinline__ void fma2(u64 &d, u64 a, u64 b) {
    asm("fma.rn.f32x2 %0,%1,%2,%0;" : "+l"(d) : "l"(a), "l"(b));
}
__device__ __forceinline__ u64 add2(u64 a, u64 b) {
    u64 r; asm("add.rn.f32x2 %0,%1,%2;" : "=l"(r) : "l"(a), "l"(b)); return r;
}

// Dual reduction: on return, lane 0's `a` = full sum of a; lane 16's `a` = full sum of b.
__device__ __forceinline__ u64 reduce_pair(u64 a, u64 b, int lane) {
    u64 af = add2(a, __shfl_xor_sync(0xffffffffu, a, 16));
    u64 bf = add2(b, __shfl_xor_sync(0xffffffffu, b, 16));
    u64 m = (lane & 16) ? bf : af;
#pragma unroll
    for (int o = 8; o; o >>= 1)
        m = add2(m, __shfl_xor_sync(0xffffffffu, m, o));
    return m;
}

// ---------------------------------------------------------------------------
// Routing: per-expert token lists (duplicate expert ids merged). One block.
// ---------------------------------------------------------------------------
__global__ void route_kernel(const int* __restrict__ tope,
                             const float* __restrict__ topw)
{
    __shared__ int   se[NT * NK];
    __shared__ float sw[NT * NK];
    const int tid = threadIdx.x;
    if (tid < NT * NK) { se[tid] = tope[tid]; sw[tid] = topw[tid]; }
    __syncthreads();
    if (tid < NE) {
        const int e = tid; int c = 0;
        for (int t = 0; t < NT; t++) {
            float r = 0.f; int hit = 0;
#pragma unroll
            for (int k = 0; k < NK; k++)
                if (se[t * NK + k] == e) { r += sw[t * NK + k]; hit = 1; }
            if (hit) { g_tok[e * NT + c] = t; g_rw[e * NT + c] = r; c++; }
        }
        g_cnt[e] = c;
    }
}

__global__ void zero_kernel(float* __restrict__ out)
{
    const int gid = blockIdx.x * blockDim.x + threadIdx.x;
    float4 z = make_float4(0.f, 0.f, 0.f, 0.f);
    float4* o4 = (float4*)out;
    for (int i = gid; i < (NT * NH) / 4; i += gridDim.x * blockDim.x) o4[i] = z;
}

// ---------------------------------------------------------------------------
// Stage A: act[e][j][f] = rw * silu(x_j . w1_f) * (x_j . v1_f)
// Warp owns rows (f0, f0+1) of both w1 and v1. All f32x2 lanes pair over h:
// a 16B load is two ready-made u64 operands -> zero packing MOVs.
// ---------------------------------------------------------------------------
template<int JT>
__device__ __forceinline__ void stageA_body(
    const float* __restrict__ w1, const float* __restrict__ v1,
    const ulonglong2* xs2, const float* srw, int e, int fbase, int jbase, int J)
{
    const int tid = threadIdx.x, warp = tid >> 5, lane = tid & 31;

#pragma unroll 1
    for (int pass = 0; pass < 4; pass++) {
        const int f0 = fbase + pass * 16 + warp * 2;
        const ulonglong2* pwa = (const ulonglong2*)(w1 + ((size_t)e * NF + f0) * NH);
        const ulonglong2* pwb = pwa + 512;
        const ulonglong2* pva = (const ulonglong2*)(v1 + ((size_t)e * NF + f0) * NH);
        const ulonglong2* pvb = pva + 512;

        u64 g0[JT], g1[JT], u0[JT], u1[JT];
#pragma unroll
        for (int j = 0; j < JT; j++) { g0[j] = 0ull; g1[j] = 0ull; u0[j] = 0ull; u1[j] = 0ull; }

        ulonglong2 cwa = __ldg(pwa + lane), cwb = __ldg(pwb + lane);
        ulonglong2 cva = __ldg(pva + lane), cvb = __ldg(pvb + lane);

#pragma unroll 1
        for (int c = 0; c < 16; c++) {
            const int qn = (c < 15) ? ((c + 1) * 32 + lane) : lane;
            const ulonglong2 nwa = __ldg(pwa + qn), nwb = __ldg(pwb + qn);
            const ulonglong2 nva = __ldg(pva + qn), nvb = __ldg(pvb + qn);

            const int qb = c * 32 + lane;
#pragma unroll
            for (int j = 0; j < JT; j++) {
                const ulonglong2 xv = xs2[j * 512 + qb];   // one LDS.128
                fma2(g0[j], cwa.x, xv.x); fma2(g0[j], cwa.y, xv.y);
                fma2(g1[j], cwb.x, xv.x); fma2(g1[j], cwb.y, xv.y);
                fma2(u0[j], cva.x, xv.x); fma2(u0[j], cva.y, xv.y);
                fma2(u1[j], cvb.x, xv.x); fma2(u1[j], cvb.y, xv.y);
            }
            cwa = nwa; cwb = nwb; cva = nva; cvb = nvb;
        }

#pragma unroll
        for (int j = 0; j < JT; j++) {
            const u64 gr = reduce_pair(g0[j], g1[j], lane);  // lane0: f0, lane16: f0+1
            const u64 ur = reduce_pair(u0[j], u1[j], lane);
            if ((lane & 15) == 0 && j < J) {
                float gl, gh, ul, uh;
                upk2(gr, gl, gh); upk2(ur, ul, uh);
                const float gv = gl + gh, uv = ul + uh;
                const float s = gv / (1.f + __expf(-gv));
                g_act[((size_t)(e * NT + jbase + j)) * NF + f0 + (lane >> 4)] = s * uv * srw[j];
            }
        }
    }
}

__global__ void __launch_bounds__(256, 1) stageA_kernel(
    const float* __restrict__ x, const float* __restrict__ w1, const float* __restrict__ v1)
{
    const int e = blockIdx.y;
    const int ftile = blockIdx.x >> 2, chunk = blockIdx.x & 3;  // chunk fastest: L2 dedup
    const int jbase = chunk * JA;
    const int cnt = g_cnt[e];
    if (jbase >= cnt) return;
    const int J  = min(JA, cnt - jbase);
    const int Jp = ((J + 3) >> 2) << 2;

    extern __shared__ float xs[];
    __shared__ int   stok[JA];
    __shared__ float srw [JA];
    const int tid = threadIdx.x;
    if (tid < JA) {
        stok[tid] = (tid < J) ? g_tok[e * NT + jbase + tid] : 0;
        srw [tid] = (tid < J) ? g_rw [e * NT + jbase + tid] : 0.f;
    }
    __syncthreads();

    float4* xs4 = (float4*)xs;
    const float4* x4 = (const float4*)x;
    for (int idx = tid; idx < Jp * 512; idx += 256) {
        const int j = idx >> 9, q = idx & 511;
        xs4[idx] = (j < J) ? __ldg(x4 + (size_t)stok[j] * 512 + q)
                           : make_float4(0.f, 0.f, 0.f, 0.f);
    }
    __syncthreads();

    const int fbase = ftile * 64;
    switch ((J + 3) >> 2) {
        case 1:  stageA_body<4 >(w1, v1, (const ulonglong2*)xs, srw, e, fbase, jbase, J); break;
        case 2:  stageA_body<8 >(w1, v1, (const ulonglong2*)xs, srw, e, fbase, jbase, J); break;
        case 3:  stageA_body<12>(w1, v1, (const ulonglong2*)xs, srw, e, fbase, jbase, J); break;
        default: stageA_body<16>(w1, v1, (const ulonglong2*)xs, srw, e, fbase, jbase, J); break;
    }
}

// ---------------------------------------------------------------------------
// Stage B: out[t] += act[e][j] @ w2_e  (rw folded into act already).
// Thread owns 4 h (2 u64 accs per j). act pre-duplicated (a,a) in smem so the
// broadcast LDS.128 feeds 4 FFMA2 with zero packing MOVs.
// ---------------------------------------------------------------------------
template<int JT>
__device__ __forceinline__ void stageB_body(
    const float* __restrict__ w2, float* __restrict__ out,
    const u64* sdup, const int* stok, int e, int h0, int f0, int J)
{
    const int tid = threadIdx.x;
    u64 A0[JT], A1[JT];
#pragma unroll
    for (int j = 0; j < JT; j++) { A0[j] = 0ull; A1[j] = 0ull; }

    const ulonglong2* wb = (const ulonglong2*)(w2 + ((size_t)e * NF + f0) * NH) + (h0 >> 2) + tid;
    ulonglong2 c0 = __ldg(wb), c1 = __ldg(wb + 512);

#pragma unroll 1
    for (int p = 0; p < 256; p++) {
        ulonglong2 n0 = c0, n1 = c1;
        if (p < 255) {
            n0 = __ldg(wb + (size_t)(2 * p + 2) * 512);
            n1 = __ldg(wb + (size_t)(2 * p + 3) * 512);
        }
#pragma unroll
        for (int j = 0; j < JT; j++) {
            const ulonglong2 av = *(const ulonglong2*)(sdup + j * 512 + 2 * p); // LDS.128 bcast
            fma2(A0[j], c0.x, av.x); fma2(A1[j], c0.y, av.x);
            fma2(A0[j], c1.x, av.y); fma2(A1[j], c1.y, av.y);
        }
        c0 = n0; c1 = n1;
    }

#pragma unroll
    for (int j = 0; j < JT; j++) {
        if (j < J) {
            float v0, v1, v2, v3;
            upk2(A0[j], v0, v1); upk2(A1[j], v2, v3);
            float* op = out + (size_t)stok[j] * NH + h0 + tid * 4;
            atomicAdd(op,     v0);
            atomicAdd(op + 1, v1);
            atomicAdd(op + 2, v2);
            atomicAdd(op + 3, v3);
        }
    }
}

__global__ void __launch_bounds__(256, 1) stageB_kernel(
    const float* __restrict__ w2, float* __restrict__ out)
{
    const int e = blockIdx.y;
    const int jc = blockIdx.z % 3, fs = blockIdx.z / 3;   // jc fastest: L2 dedup
    const int jbase = jc * JB;
    const int cnt = g_cnt[e];
    if (jbase >= cnt) return;
    const int J  = min(JB, cnt - jbase);
    const int Jp = ((J + 3) >> 2) << 2;
    const int h0 = blockIdx.x * 1024, f0 = fs * 512;

    extern __shared__ u64 sdup[];                        // [JB][512] duplicated act
    __shared__ int stok[JB];
    const int tid = threadIdx.x;
    if (tid < JB) stok[tid] = (tid < J) ? g_tok[e * NT + jbase + tid] : 0;
    __syncthreads();

    for (int idx = tid; idx < Jp * 512; idx += 256) {
        const int j = idx >> 9, q = idx & 511;
        const float a = (j < J)
            ? g_act[((size_t)(e * NT + jbase + j)) * NF + f0 + q] : 0.f;
        sdup[idx] = pk2(a, a);
    }
    __syncthreads();

    switch ((J + 3) >> 2) {
        case 1:  stageB_body<4 >(w2, out, sdup, stok, e, h0, f0, J); break;
        case 2:  stageB_body<8 >(w2, out, sdup, stok, e, h0, f0, J); break;
        case 3:  stageB_body<12>(w2, out, sdup, stok, e, h0, f0, J); break;
        case 4:  stageB_body<16>(w2, out, sdup, stok, e, h0, f0, J); break;
        case 5:  stageB_body<20>(w2, out, sdup, stok, e, h0, f0, J); break;
        default: stageB_body<24>(w2, out, sdup, stok, e, h0, f0, J); break;
    }
}

// ---------------------------------------------------------------------------
extern "C" void kernel_launch(void* const* d_in, const int* in_sizes, int n_in,
                              void* d_out, int out_size)
{
    const float* x    = (const float*)d_in[0];
    const float* topw = (const float*)d_in[2];
    const int*   tope = (const int*)  d_in[3];
    const float* w1   = (const float*)d_in[4];
    const float* v1   = (const float*)d_in[5];
    const float* w2   = (const float*)d_in[6];
    float* out = (float*)d_out;

    cudaFuncSetAttribute(stageA_kernel, cudaFuncAttributeMaxDynamicSharedMemorySize, JA * NH * 4);
    cudaFuncSetAttribute(stageB_kernel, cudaFuncAttributeMaxDynamicSharedMemorySize, JB * 512 * 8);

    route_kernel<<<1, 256>>>(tope, topw);
    zero_kernel<<<64, 256>>>(out);
    stageA_kernel<<<dim3(256, NE), 256, JA * NH * 4>>>(x, w1, v1);
    stageB_kernel<<<dim3(2, NE, 24), 256, JB * 512 * 8>>>(w2, out);
}

// round 5
// speedup vs baseline: 1.9452x; 1.4577x over previous
#include <cuda_runtime.h>

#define NE 16
#define NK 4
#define NH 2048
#define NF 4096
#define NT 64
#define JA 16
#define JB 16

typedef unsigned long long u64;

__device__ float g_act[(size_t)NE * NT * NF];   // 16.8 MB scratch
__device__ int   g_cnt[NE];
__device__ int   g_tok[NE * NT];
__device__ float g_rw [NE * NT];

__device__ __forceinline__ u64 pk2(float lo, float hi) {
    u64 r; asm("mov.b64 %0,{%1,%2};" : "=l"(r) : "f"(lo), "f"(hi)); return r;
}
__device__ __forceinline__ void upk2(u64 v, float &lo, float &hi) {
    asm("mov.b64 {%0,%1},%2;" : "=f"(lo), "=f"(hi) : "l"(v));
}
__device__ __forceinline__ void fma2(u64 &d, u64 a, u64 b) {
    asm("fma.rn.f32x2 %0,%1,%2,%0;" : "+l"(d) : "l"(a), "l"(b));
}
__device__ __forceinline__ u64 add2(u64 a, u64 b) {
    u64 r; asm("add.rn.f32x2 %0,%1,%2;" : "=l"(r) : "l"(a), "l"(b)); return r;
}
__device__ __forceinline__ void red4(float* p, float a, float b, float c, float d) {
    asm volatile("red.global.add.v4.f32 [%0], {%1,%2,%3,%4};"
                 :: "l"(p), "f"(a), "f"(b), "f"(c), "f"(d) : "memory");
}
// Dual reduction: lane 0 ends with full sum of a, lane 16 with full sum of b.
__device__ __forceinline__ u64 reduce_pair(u64 a, u64 b, int lane) {
    u64 af = add2(a, __shfl_xor_sync(0xffffffffu, a, 16));
    u64 bf = add2(b, __shfl_xor_sync(0xffffffffu, b, 16));
    u64 m = (lane & 16) ? bf : af;
#pragma unroll
    for (int o = 8; o; o >>= 1)
        m = add2(m, __shfl_xor_sync(0xffffffffu, m, o));
    return m;
}

// ---------------------------------------------------------------------------
__global__ void route_kernel(const int* __restrict__ tope,
                             const float* __restrict__ topw)
{
    __shared__ int   se[NT * NK];
    __shared__ float sw[NT * NK];
    const int tid = threadIdx.x;
    if (tid < NT * NK) { se[tid] = tope[tid]; sw[tid] = topw[tid]; }
    __syncthreads();
    if (tid < NE) {
        const int e = tid; int c = 0;
        for (int t = 0; t < NT; t++) {
            float r = 0.f; int hit = 0;
#pragma unroll
            for (int k = 0; k < NK; k++)
                if (se[t * NK + k] == e) { r += sw[t * NK + k]; hit = 1; }
            if (hit) { g_tok[e * NT + c] = t; g_rw[e * NT + c] = r; c++; }
        }
        g_cnt[e] = c;
    }
}

__global__ void zero_kernel(float* __restrict__ out)
{
    const int gid = blockIdx.x * blockDim.x + threadIdx.x;
    float4 z = make_float4(0.f, 0.f, 0.f, 0.f);
    float4* o4 = (float4*)out;
    for (int i = gid; i < (NT * NH) / 4; i += gridDim.x * blockDim.x) o4[i] = z;
}

// ---------------------------------------------------------------------------
// Stage A: act[e][j][f] = rw * silu(x.w1_f) * (x.v1_f)
// Warp owns f-rows (f0,f0+1) of w1 AND v1 (4 streams). 8 FFMA2 per LDS.128
// (crossbar at cap). D=4 register ring on each stream hides DRAM latency.
// ---------------------------------------------------------------------------
template<int JT>
__device__ __forceinline__ void stageA_body(
    const float* __restrict__ w1, const float* __restrict__ v1,
    const ulonglong2* xs2, const float* srw, int e, int fbase, int jbase, int J)
{
    const int tid = threadIdx.x, warp = tid >> 5, lane = tid & 31;

#pragma unroll 1
    for (int pass = 0; pass < 4; pass++) {
        const int f0 = fbase + pass * 16 + warp * 2;
        const ulonglong2* pwa = (const ulonglong2*)(w1 + ((size_t)e * NF + f0) * NH);
        const ulonglong2* pwb = pwa + 512;
        const ulonglong2* pva = (const ulonglong2*)(v1 + ((size_t)e * NF + f0) * NH);
        const ulonglong2* pvb = pva + 512;

        u64 g0[JT], g1[JT], u0[JT], u1[JT];
#pragma unroll
        for (int j = 0; j < JT; j++) { g0[j] = 0ull; g1[j] = 0ull; u0[j] = 0ull; u1[j] = 0ull; }

        ulonglong2 rwa[4], rwb[4], rva[4], rvb[4];
#pragma unroll
        for (int s = 0; s < 4; s++) {
            const int q = s * 32 + lane;
            rwa[s] = __ldg(pwa + q); rwb[s] = __ldg(pwb + q);
            rva[s] = __ldg(pva + q); rvb[s] = __ldg(pvb + q);
        }

#pragma unroll 4
        for (int c = 0; c < 16; c++) {
            const int sl = c & 3;
            const int qb = c * 32 + lane;
#pragma unroll
            for (int j = 0; j < JT; j++) {
                const ulonglong2 xv = xs2[j * 512 + qb];   // one LDS.128, 8 FFMA2
                fma2(g0[j], rwa[sl].x, xv.x); fma2(g0[j], rwa[sl].y, xv.y);
                fma2(g1[j], rwb[sl].x, xv.x); fma2(g1[j], rwb[sl].y, xv.y);
                fma2(u0[j], rva[sl].x, xv.x); fma2(u0[j], rva[sl].y, xv.y);
                fma2(u1[j], rvb[sl].x, xv.x); fma2(u1[j], rvb[sl].y, xv.y);
            }
            if (c < 12) {
                const int q = (c + 4) * 32 + lane;
                rwa[sl] = __ldg(pwa + q); rwb[sl] = __ldg(pwb + q);
                rva[sl] = __ldg(pva + q); rvb[sl] = __ldg(pvb + q);
            }
        }

#pragma unroll
        for (int j = 0; j < JT; j++) {
            const u64 gr = reduce_pair(g0[j], g1[j], lane);  // lane0: f0, lane16: f0+1
            const u64 ur = reduce_pair(u0[j], u1[j], lane);
            if ((lane & 15) == 0 && j < J) {
                float gl, gh, ul, uh;
                upk2(gr, gl, gh); upk2(ur, ul, uh);
                const float gv = gl + gh, uv = ul + uh;
                const float s = gv / (1.f + __expf(-gv));
                g_act[((size_t)(e * NT + jbase + j)) * NF + f0 + (lane >> 4)] = s * uv * srw[j];
            }
        }
    }
}

__global__ void __launch_bounds__(256) stageA_kernel(
    const float* __restrict__ x, const float* __restrict__ w1, const float* __restrict__ v1)
{
    const int e = blockIdx.y;
    const int ftile = blockIdx.x >> 2, chunk = blockIdx.x & 3;  // chunk fastest: L2 dedup
    const int jbase = chunk * JA;
    const int cnt = g_cnt[e];
    if (jbase >= cnt) return;
    const int J  = min(JA, cnt - jbase);
    const int Jp = ((J + 3) >> 2) << 2;

    extern __shared__ __align__(16) float xs[];
    __shared__ int   stok[JA];
    __shared__ float srw [JA];
    const int tid = threadIdx.x;
    if (tid < JA) {
        stok[tid] = (tid < J) ? g_tok[e * NT + jbase + tid] : 0;
        srw [tid] = (tid < J) ? g_rw [e * NT + jbase + tid] : 0.f;
    }
    __syncthreads();

    float4* xs4 = (float4*)xs;
    const float4* x4 = (const float4*)x;
    for (int idx = tid; idx < Jp * 512; idx += 256) {
        const int j = idx >> 9, q = idx & 511;
        xs4[idx] = (j < J) ? __ldg(x4 + (size_t)stok[j] * 512 + q)
                           : make_float4(0.f, 0.f, 0.f, 0.f);
    }
    __syncthreads();

    const int fbase = ftile * 64;
    switch ((J + 3) >> 2) {
        case 1:  stageA_body<4 >(w1, v1, (const ulonglong2*)xs, srw, e, fbase, jbase, J); break;
        case 2:  stageA_body<8 >(w1, v1, (const ulonglong2*)xs, srw, e, fbase, jbase, J); break;
        case 3:  stageA_body<12>(w1, v1, (const ulonglong2*)xs, srw, e, fbase, jbase, J); break;
        default: stageA_body<16>(w1, v1, (const ulonglong2*)xs, srw, e, fbase, jbase, J); break;
    }
}

// ---------------------------------------------------------------------------
// Stage B: out[t] += act[e][j] @ w2_e (rw already folded into act).
// Thread owns 8 h (4 u64 accs/j). Per 2-f step: 1 broadcast LDS.128 feeds
// 8 FFMA2 per j. D=4 ring on the 4 w2 streams. v4 red atomics epilogue.
// ---------------------------------------------------------------------------
template<int JT>
__device__ __forceinline__ void stageB_body(
    const float* __restrict__ w2, float* __restrict__ out,
    const ulonglong2* sdup2, const int* stok, int e, int f0, int J)
{
    const int tid = threadIdx.x;                 // 256 threads, h = tid*8
    u64 A0[JT], A1[JT], A2[JT], A3[JT];
#pragma unroll
    for (int j = 0; j < JT; j++) { A0[j] = 0ull; A1[j] = 0ull; A2[j] = 0ull; A3[j] = 0ull; }

    const ulonglong2* wb = (const ulonglong2*)(w2 + ((size_t)e * NF + f0) * NH) + tid * 2;

    ulonglong2 R0[4], R1[4], R2[4], R3[4];       // [slot]: rows (2s: h0..3, h4..7), (2s+1: ...)
#pragma unroll
    for (int s = 0; s < 4; s++) {
        R0[s] = __ldg(wb + (size_t)(2 * s    ) * 512);
        R1[s] = __ldg(wb + (size_t)(2 * s    ) * 512 + 1);
        R2[s] = __ldg(wb + (size_t)(2 * s + 1) * 512);
        R3[s] = __ldg(wb + (size_t)(2 * s + 1) * 512 + 1);
    }

#pragma unroll 4
    for (int s = 0; s < 128; s++) {
        const int sl = s & 3;
#pragma unroll
        for (int j = 0; j < JT; j++) {
            const ulonglong2 av = sdup2[j * 128 + s];  // broadcast LDS.128
            fma2(A0[j], R0[sl].x, av.x); fma2(A1[j], R0[sl].y, av.x);
            fma2(A2[j], R1[sl].x, av.x); fma2(A3[j], R1[sl].y, av.x);
            fma2(A0[j], R2[sl].x, av.y); fma2(A1[j], R2[sl].y, av.y);
            fma2(A2[j], R3[sl].x, av.y); fma2(A3[j], R3[sl].y, av.y);
        }
        if (s < 124) {
            const int t = s + 4;
            R0[sl] = __ldg(wb + (size_t)(2 * t    ) * 512);
            R1[sl] = __ldg(wb + (size_t)(2 * t    ) * 512 + 1);
            R2[sl] = __ldg(wb + (size_t)(2 * t + 1) * 512);
            R3[sl] = __ldg(wb + (size_t)(2 * t + 1) * 512 + 1);
        }
    }

#pragma unroll
    for (int j = 0; j < JT; j++) {
        if (j < J) {
            float a0, a1, a2, a3, a4, a5, a6, a7;
            upk2(A0[j], a0, a1); upk2(A1[j], a2, a3);
            upk2(A2[j], a4, a5); upk2(A3[j], a6, a7);
            float* op = out + (size_t)stok[j] * NH + tid * 8;
            red4(op,     a0, a1, a2, a3);
            red4(op + 4, a4, a5, a6, a7);
        }
    }
}

__global__ void __launch_bounds__(256) stageB_kernel(
    const float* __restrict__ w2, float* __restrict__ out)
{
    const int jc = blockIdx.x, e = blockIdx.y;            // jc fastest: L2 dedup on w2
    const int jbase = jc * JB;
    const int cnt = g_cnt[e];
    if (jbase >= cnt) return;
    const int J  = min(JB, cnt - jbase);
    const int Jp = ((J + 3) >> 2) << 2;
    const int f0 = blockIdx.z * 256;

    extern __shared__ __align__(16) u64 sdup[];           // [JB][256] duplicated act
    __shared__ int stok[JB];
    const int tid = threadIdx.x;
    if (tid < JB) stok[tid] = (tid < J) ? g_tok[e * NT + jbase + tid] : 0;
    __syncthreads();

    for (int idx = tid; idx < Jp * 256; idx += 256) {
        const int j = idx >> 8, q = idx & 255;
        const float a = (j < J)
            ? g_act[((size_t)(e * NT + jbase + j)) * NF + f0 + q] : 0.f;
        sdup[idx] = pk2(a, a);
    }
    __syncthreads();

    switch ((J + 3) >> 2) {
        case 1:  stageB_body<4 >(w2, out, (const ulonglong2*)sdup, stok, e, f0, J); break;
        case 2:  stageB_body<8 >(w2, out, (const ulonglong2*)sdup, stok, e, f0, J); break;
        case 3:  stageB_body<12>(w2, out, (const ulonglong2*)sdup, stok, e, f0, J); break;
        default: stageB_body<16>(w2, out, (const ulonglong2*)sdup, stok, e, f0, J); break;
    }
}

// ---------------------------------------------------------------------------
extern "C" void kernel_launch(void* const* d_in, const int* in_sizes, int n_in,
                              void* d_out, int out_size)
{
    const float* x    = (const float*)d_in[0];
    const float* topw = (const float*)d_in[2];
    const int*   tope = (const int*)  d_in[3];
    const float* w1   = (const float*)d_in[4];
    const float* v1   = (const float*)d_in[5];
    const float* w2   = (const float*)d_in[6];
    float* out = (float*)d_out;

    cudaFuncSetAttribute(stageA_kernel, cudaFuncAttributeMaxDynamicSharedMemorySize, JA * NH * 4);
    cudaFuncSetAttribute(stageB_kernel, cudaFuncAttributeMaxDynamicSharedMemorySize, JB * 256 * 8);

    route_kernel<<<1, 256>>>(tope, topw);
    zero_kernel<<<64, 256>>>(out);
    stageA_kernel<<<dim3(256, NE), 256, JA * NH * 4>>>(x, w1, v1);
    stageB_kernel<<<dim3(4, NE, 16), 256, JB * 256 * 8>>>(w2, out);
}

// round 6
// speedup vs baseline: 2.3102x; 1.1877x over previous
#include <cuda_runtime.h>

#define NE 16
#define NK 4
#define NH 2048
#define NF 4096
#define NT 64
#define JA 8
#define JB 8

typedef unsigned long long u64;

__device__ float g_act[(size_t)NE * NT * NF];   // 16.8 MB scratch
__device__ int   g_cnt[NE];
__device__ int   g_tok[NE * NT];
__device__ float g_rw [NE * NT];

__device__ __forceinline__ u64 pk2(float lo, float hi) {
    u64 r; asm("mov.b64 %0,{%1,%2};" : "=l"(r) : "f"(lo), "f"(hi)); return r;
}
__device__ __forceinline__ void upk2(u64 v, float &lo, float &hi) {
    asm("mov.b64 {%0,%1},%2;" : "=f"(lo), "=f"(hi) : "l"(v));
}
__device__ __forceinline__ void fma2(u64 &d, u64 a, u64 b) {
    asm("fma.rn.f32x2 %0,%1,%2,%0;" : "+l"(d) : "l"(a), "l"(b));
}
__device__ __forceinline__ u64 add2(u64 a, u64 b) {
    u64 r; asm("add.rn.f32x2 %0,%1,%2;" : "=l"(r) : "l"(a), "l"(b)); return r;
}
__device__ __forceinline__ void red4(float* p, float a, float b, float c, float d) {
    asm volatile("red.global.add.v4.f32 [%0], {%1,%2,%3,%4};"
                 :: "l"(p), "f"(a), "f"(b), "f"(c), "f"(d) : "memory");
}
// Dual reduction: lane 0 ends with full sum of a, lane 16 with full sum of b.
__device__ __forceinline__ u64 reduce_pair(u64 a, u64 b, int lane) {
    u64 af = add2(a, __shfl_xor_sync(0xffffffffu, a, 16));
    u64 bf = add2(b, __shfl_xor_sync(0xffffffffu, b, 16));
    u64 m = (lane & 16) ? bf : af;
#pragma unroll
    for (int o = 8; o; o >>= 1)
        m = add2(m, __shfl_xor_sync(0xffffffffu, m, o));
    return m;
}

// ---------------------------------------------------------------------------
__global__ void route_kernel(const int* __restrict__ tope,
                             const float* __restrict__ topw)
{
    __shared__ int   se[NT * NK];
    __shared__ float sw[NT * NK];
    const int tid = threadIdx.x;
    if (tid < NT * NK) { se[tid] = tope[tid]; sw[tid] = topw[tid]; }
    __syncthreads();
    if (tid < NE) {
        const int e = tid; int c = 0;
        for (int t = 0; t < NT; t++) {
            float r = 0.f; int hit = 0;
#pragma unroll
            for (int k = 0; k < NK; k++)
                if (se[t * NK + k] == e) { r += sw[t * NK + k]; hit = 1; }
            if (hit) { g_tok[e * NT + c] = t; g_rw[e * NT + c] = r; c++; }
        }
        g_cnt[e] = c;
    }
}

__global__ void zero_kernel(float* __restrict__ out)
{
    const int gid = blockIdx.x * blockDim.x + threadIdx.x;
    float4 z = make_float4(0.f, 0.f, 0.f, 0.f);
    float4* o4 = (float4*)out;
    for (int i = gid; i < (NT * NH) / 4; i += gridDim.x * blockDim.x) o4[i] = z;
}

// ---------------------------------------------------------------------------
// Stage A: act[e][j][f] = rw * silu(x.w1_f) * (x.v1_f)
// Warp owns f-rows (f0,f0+1) of w1 AND v1 (4 streams). 8 FFMA2 per LDS.128.
// D=2 register ring per stream; JT<=8 keeps regs <=128 -> 2 CTAs/SM.
// ---------------------------------------------------------------------------
template<int JT>
__device__ __forceinline__ void stageA_body(
    const float* __restrict__ w1, const float* __restrict__ v1,
    const ulonglong2* xs2, const float* srw, int e, int fbase, int jbase, int J)
{
    const int tid = threadIdx.x, warp = tid >> 5, lane = tid & 31;

#pragma unroll 1
    for (int pass = 0; pass < 4; pass++) {
        const int f0 = fbase + pass * 16 + warp * 2;
        const ulonglong2* pwa = (const ulonglong2*)(w1 + ((size_t)e * NF + f0) * NH);
        const ulonglong2* pwb = pwa + 512;
        const ulonglong2* pva = (const ulonglong2*)(v1 + ((size_t)e * NF + f0) * NH);
        const ulonglong2* pvb = pva + 512;

        u64 g0[JT], g1[JT], u0[JT], u1[JT];
#pragma unroll
        for (int j = 0; j < JT; j++) { g0[j] = 0ull; g1[j] = 0ull; u0[j] = 0ull; u1[j] = 0ull; }

        ulonglong2 rwa[2], rwb[2], rva[2], rvb[2];
#pragma unroll
        for (int s = 0; s < 2; s++) {
            const int q = s * 32 + lane;
            rwa[s] = __ldg(pwa + q); rwb[s] = __ldg(pwb + q);
            rva[s] = __ldg(pva + q); rvb[s] = __ldg(pvb + q);
        }

#pragma unroll 2
        for (int c = 0; c < 16; c++) {
            const int sl = c & 1;
            const int qb = c * 32 + lane;
#pragma unroll
            for (int j = 0; j < JT; j++) {
                const ulonglong2 xv = xs2[j * 512 + qb];   // one LDS.128, 8 FFMA2
                fma2(g0[j], rwa[sl].x, xv.x); fma2(g0[j], rwa[sl].y, xv.y);
                fma2(g1[j], rwb[sl].x, xv.x); fma2(g1[j], rwb[sl].y, xv.y);
                fma2(u0[j], rva[sl].x, xv.x); fma2(u0[j], rva[sl].y, xv.y);
                fma2(u1[j], rvb[sl].x, xv.x); fma2(u1[j], rvb[sl].y, xv.y);
            }
            if (c < 14) {
                const int q = (c + 2) * 32 + lane;
                rwa[sl] = __ldg(pwa + q); rwb[sl] = __ldg(pwb + q);
                rva[sl] = __ldg(pva + q); rvb[sl] = __ldg(pvb + q);
            }
        }

#pragma unroll
        for (int j = 0; j < JT; j++) {
            const u64 gr = reduce_pair(g0[j], g1[j], lane);  // lane0: f0, lane16: f0+1
            const u64 ur = reduce_pair(u0[j], u1[j], lane);
            if ((lane & 15) == 0 && j < J) {
                float gl, gh, ul, uh;
                upk2(gr, gl, gh); upk2(ur, ul, uh);
                const float gv = gl + gh, uv = ul + uh;
                const float s = gv / (1.f + __expf(-gv));
                g_act[((size_t)(e * NT + jbase + j)) * NF + f0 + (lane >> 4)] = s * uv * srw[j];
            }
        }
    }
}

__global__ void __launch_bounds__(256, 2) stageA_kernel(
    const float* __restrict__ x, const float* __restrict__ w1, const float* __restrict__ v1)
{
    const int e = blockIdx.y;
    const int ftile = blockIdx.x >> 3, chunk = blockIdx.x & 7;  // chunk fastest: L2 dedup
    const int jbase = chunk * JA;
    const int cnt = g_cnt[e];
    if (jbase >= cnt) return;
    const int J  = min(JA, cnt - jbase);
    const int Jp = ((J + 3) >> 2) << 2;

    extern __shared__ __align__(16) float xs[];
    __shared__ int   stok[JA];
    __shared__ float srw [JA];
    const int tid = threadIdx.x;
    if (tid < JA) {
        stok[tid] = (tid < J) ? g_tok[e * NT + jbase + tid] : 0;
        srw [tid] = (tid < J) ? g_rw [e * NT + jbase + tid] : 0.f;
    }
    __syncthreads();

    float4* xs4 = (float4*)xs;
    const float4* x4 = (const float4*)x;
    for (int idx = tid; idx < Jp * 512; idx += 256) {
        const int j = idx >> 9, q = idx & 511;
        xs4[idx] = (j < J) ? __ldg(x4 + (size_t)stok[j] * 512 + q)
                           : make_float4(0.f, 0.f, 0.f, 0.f);
    }
    __syncthreads();

    const int fbase = ftile * 64;
    if (((J + 3) >> 2) == 1)
        stageA_body<4>(w1, v1, (const ulonglong2*)xs, srw, e, fbase, jbase, J);
    else
        stageA_body<8>(w1, v1, (const ulonglong2*)xs, srw, e, fbase, jbase, J);
}

// ---------------------------------------------------------------------------
// Stage B: out[t] += act[e][j] @ w2_e (rw already folded into act).
// Thread owns 8 h (4 u64 accs/j). Per 2-f step: 1 broadcast LDS.128 feeds
// 8 FFMA2 per j. D=2 ring on the 4 w2 streams. v4 red atomics epilogue.
// ---------------------------------------------------------------------------
template<int JT>
__device__ __forceinline__ void stageB_body(
    const float* __restrict__ w2, float* __restrict__ out,
    const ulonglong2* sdup2, const int* stok, int e, int f0, int J)
{
    const int tid = threadIdx.x;                 // 256 threads, h = tid*8
    u64 A0[JT], A1[JT], A2[JT], A3[JT];
#pragma unroll
    for (int j = 0; j < JT; j++) { A0[j] = 0ull; A1[j] = 0ull; A2[j] = 0ull; A3[j] = 0ull; }

    const ulonglong2* wb = (const ulonglong2*)(w2 + ((size_t)e * NF + f0) * NH) + tid * 2;

    ulonglong2 R0[2], R1[2], R2[2], R3[2];       // [slot]: rows 2s (h0..3,h4..7) and 2s+1
#pragma unroll
    for (int s = 0; s < 2; s++) {
        R0[s] = __ldg(wb + (size_t)(2 * s    ) * 512);
        R1[s] = __ldg(wb + (size_t)(2 * s    ) * 512 + 1);
        R2[s] = __ldg(wb + (size_t)(2 * s + 1) * 512);
        R3[s] = __ldg(wb + (size_t)(2 * s + 1) * 512 + 1);
    }

#pragma unroll 2
    for (int s = 0; s < 128; s++) {
        const int sl = s & 1;
#pragma unroll
        for (int j = 0; j < JT; j++) {
            const ulonglong2 av = sdup2[j * 128 + s];  // broadcast LDS.128
            fma2(A0[j], R0[sl].x, av.x); fma2(A1[j], R0[sl].y, av.x);
            fma2(A2[j], R1[sl].x, av.x); fma2(A3[j], R1[sl].y, av.x);
            fma2(A0[j], R2[sl].x, av.y); fma2(A1[j], R2[sl].y, av.y);
            fma2(A2[j], R3[sl].x, av.y); fma2(A3[j], R3[sl].y, av.y);
        }
        if (s < 126) {
            const int t = s + 2;
            R0[sl] = __ldg(wb + (size_t)(2 * t    ) * 512);
            R1[sl] = __ldg(wb + (size_t)(2 * t    ) * 512 + 1);
            R2[sl] = __ldg(wb + (size_t)(2 * t + 1) * 512);
            R3[sl] = __ldg(wb + (size_t)(2 * t + 1) * 512 + 1);
        }
    }

#pragma unroll
    for (int j = 0; j < JT; j++) {
        if (j < J) {
            float a0, a1, a2, a3, a4, a5, a6, a7;
            upk2(A0[j], a0, a1); upk2(A1[j], a2, a3);
            upk2(A2[j], a4, a5); upk2(A3[j], a6, a7);
            float* op = out + (size_t)stok[j] * NH + tid * 8;
            red4(op,     a0, a1, a2, a3);
            red4(op + 4, a4, a5, a6, a7);
        }
    }
}

__global__ void __launch_bounds__(256, 2) stageB_kernel(
    const float* __restrict__ w2, float* __restrict__ out)
{
    const int jc = blockIdx.x, e = blockIdx.y;            // jc fastest: L2 dedup on w2
    const int jbase = jc * JB;
    const int cnt = g_cnt[e];
    if (jbase >= cnt) return;
    const int J  = min(JB, cnt - jbase);
    const int Jp = ((J + 3) >> 2) << 2;
    const int f0 = blockIdx.z * 256;

    extern __shared__ __align__(16) u64 sdup[];           // [JB][256] duplicated act
    __shared__ int stok[JB];
    const int tid = threadIdx.x;
    if (tid < JB) stok[tid] = (tid < J) ? g_tok[e * NT + jbase + tid] : 0;
    __syncthreads();

    for (int idx = tid; idx < Jp * 256; idx += 256) {
        const int j = idx >> 8, q = idx & 255;
        const float a = (j < J)
            ? g_act[((size_t)(e * NT + jbase + j)) * NF + f0 + q] : 0.f;
        sdup[idx] = pk2(a, a);
    }
    __syncthreads();

    if (((J + 3) >> 2) == 1)
        stageB_body<4>(w2, out, (const ulonglong2*)sdup, stok, e, f0, J);
    else
        stageB_body<8>(w2, out, (const ulonglong2*)sdup, stok, e, f0, J);
}

// ---------------------------------------------------------------------------
extern "C" void kernel_launch(void* const* d_in, const int* in_sizes, int n_in,
                              void* d_out, int out_size)
{
    const float* x    = (const float*)d_in[0];
    const float* topw = (const float*)d_in[2];
    const int*   tope = (const int*)  d_in[3];
    const float* w1   = (const float*)d_in[4];
    const float* v1   = (const float*)d_in[5];
    const float* w2   = (const float*)d_in[6];
    float* out = (float*)d_out;

    cudaFuncSetAttribute(stageA_kernel, cudaFuncAttributeMaxDynamicSharedMemorySize, JA * NH * 4);
    cudaFuncSetAttribute(stageB_kernel, cudaFuncAttributeMaxDynamicSharedMemorySize, JB * 256 * 8);

    route_kernel<<<1, 256>>>(tope, topw);
    zero_kernel<<<64, 256>>>(out);
    stageA_kernel<<<dim3(512, NE), 256, JA * NH * 4>>>(x, w1, v1);
    stageB_kernel<<<dim3(8, NE, 16), 256, JB * 256 * 8>>>(w2, out);
}

// round 7
// speedup vs baseline: 2.3777x; 1.0292x over previous
#include <cuda_runtime.h>

#define NE 16
#define NK 4
#define NH 2048
#define NF 4096
#define NT 64
#define JA 8
#define JB 8

typedef unsigned long long u64;

__device__ float g_act[(size_t)NE * NT * NF];   // 16.8 MB scratch
__device__ int   g_cnt[NE];
__device__ int   g_tok[NE * NT];
__device__ float g_rw [NE * NT];

__device__ __forceinline__ u64 pk2(float lo, float hi) {
    u64 r; asm("mov.b64 %0,{%1,%2};" : "=l"(r) : "f"(lo), "f"(hi)); return r;
}
__device__ __forceinline__ void upk2(u64 v, float &lo, float &hi) {
    asm("mov.b64 {%0,%1},%2;" : "=f"(lo), "=f"(hi) : "l"(v));
}
__device__ __forceinline__ void fma2(u64 &d, u64 a, u64 b) {
    asm("fma.rn.f32x2 %0,%1,%2,%0;" : "+l"(d) : "l"(a), "l"(b));
}
__device__ __forceinline__ u64 add2(u64 a, u64 b) {
    u64 r; asm("add.rn.f32x2 %0,%1,%2;" : "=l"(r) : "l"(a), "l"(b)); return r;
}
__device__ __forceinline__ void red4(float* p, float a, float b, float c, float d) {
    asm volatile("red.global.add.v4.f32 [%0], {%1,%2,%3,%4};"
                 :: "l"(p), "f"(a), "f"(b), "f"(c), "f"(d) : "memory");
}
// Dual reduction: lane 0 ends with full sum of a, lane 16 with full sum of b.
__device__ __forceinline__ u64 reduce_pair(u64 a, u64 b, int lane) {
    u64 af = add2(a, __shfl_xor_sync(0xffffffffu, a, 16));
    u64 bf = add2(b, __shfl_xor_sync(0xffffffffu, b, 16));
    u64 m = (lane & 16) ? bf : af;
#pragma unroll
    for (int o = 8; o; o >>= 1)
        m = add2(m, __shfl_xor_sync(0xffffffffu, m, o));
    return m;
}

// ---------------------------------------------------------------------------
// Setup: block 0 builds routing tables; all blocks zero the output.
// ---------------------------------------------------------------------------
__global__ void setup_kernel(const int* __restrict__ tope,
                             const float* __restrict__ topw,
                             float* __restrict__ out)
{
    const int gid = blockIdx.x * blockDim.x + threadIdx.x;
    float4 z = make_float4(0.f, 0.f, 0.f, 0.f);
    float4* o4 = (float4*)out;
    for (int i = gid; i < (NT * NH) / 4; i += gridDim.x * blockDim.x) o4[i] = z;

    if (blockIdx.x == 0) {
        __shared__ int   se[NT * NK];
        __shared__ float sw[NT * NK];
        const int tid = threadIdx.x;
        if (tid < NT * NK) { se[tid] = tope[tid]; sw[tid] = topw[tid]; }
        __syncthreads();
        if (tid < NE) {
            const int e = tid; int c = 0;
            for (int t = 0; t < NT; t++) {
                float r = 0.f; int hit = 0;
#pragma unroll
                for (int k = 0; k < NK; k++)
                    if (se[t * NK + k] == e) { r += sw[t * NK + k]; hit = 1; }
                if (hit) { g_tok[e * NT + c] = t; g_rw[e * NT + c] = r; c++; }
            }
            g_cnt[e] = c;
        }
    }
}

// ---------------------------------------------------------------------------
// Stage A: act[e][j][f] = rw * silu(x.w1_f) * (x.v1_f)
// Warp owns f-rows (f0,f0+1) of w1 AND v1 (4 streams). 8 FFMA2 per LDS.128.
// D=2 register ring per stream; JT<=8 keeps regs <=128 -> 2 CTAs/SM.
// ---------------------------------------------------------------------------
template<int JT>
__device__ __forceinline__ void stageA_body(
    const float* __restrict__ w1, const float* __restrict__ v1,
    const ulonglong2* xs2, const float* srw, int e, int fbase, int jbase, int J)
{
    const int tid = threadIdx.x, warp = tid >> 5, lane = tid & 31;

#pragma unroll 1
    for (int pass = 0; pass < 4; pass++) {
        const int f0 = fbase + pass * 16 + warp * 2;
        const ulonglong2* pwa = (const ulonglong2*)(w1 + ((size_t)e * NF + f0) * NH);
        const ulonglong2* pwb = pwa + 512;
        const ulonglong2* pva = (const ulonglong2*)(v1 + ((size_t)e * NF + f0) * NH);
        const ulonglong2* pvb = pva + 512;

        u64 g0[JT], g1[JT], u0[JT], u1[JT];
#pragma unroll
        for (int j = 0; j < JT; j++) { g0[j] = 0ull; g1[j] = 0ull; u0[j] = 0ull; u1[j] = 0ull; }

        ulonglong2 rwa[2], rwb[2], rva[2], rvb[2];
#pragma unroll
        for (int s = 0; s < 2; s++) {
            const int q = s * 32 + lane;
            rwa[s] = __ldg(pwa + q); rwb[s] = __ldg(pwb + q);
            rva[s] = __ldg(pva + q); rvb[s] = __ldg(pvb + q);
        }

#pragma unroll 2
        for (int c = 0; c < 16; c++) {
            const int sl = c & 1;
            const int qb = c * 32 + lane;
#pragma unroll
            for (int j = 0; j < JT; j++) {
                const ulonglong2 xv = xs2[j * 512 + qb];   // one LDS.128, 8 FFMA2
                fma2(g0[j], rwa[sl].x, xv.x); fma2(g0[j], rwa[sl].y, xv.y);
                fma2(g1[j], rwb[sl].x, xv.x); fma2(g1[j], rwb[sl].y, xv.y);
                fma2(u0[j], rva[sl].x, xv.x); fma2(u0[j], rva[sl].y, xv.y);
                fma2(u1[j], rvb[sl].x, xv.x); fma2(u1[j], rvb[sl].y, xv.y);
            }
            if (c < 14) {
                const int q = (c + 2) * 32 + lane;
                rwa[sl] = __ldg(pwa + q); rwb[sl] = __ldg(pwb + q);
                rva[sl] = __ldg(pva + q); rvb[sl] = __ldg(pvb + q);
            }
        }

#pragma unroll
        for (int j = 0; j < JT; j++) {
            const u64 gr = reduce_pair(g0[j], g1[j], lane);  // lane0: f0, lane16: f0+1
            const u64 ur = reduce_pair(u0[j], u1[j], lane);
            if ((lane & 15) == 0 && j < J) {
                float gl, gh, ul, uh;
                upk2(gr, gl, gh); upk2(ur, ul, uh);
                const float gv = gl + gh, uv = ul + uh;
                const float s = gv / (1.f + __expf(-gv));
                g_act[((size_t)(e * NT + jbase + j)) * NF + f0 + (lane >> 4)] = s * uv * srw[j];
            }
        }
    }
}

__global__ void __launch_bounds__(256, 2) stageA_kernel(
    const float* __restrict__ x, const float* __restrict__ w1, const float* __restrict__ v1)
{
    const int e = blockIdx.y;
    const int ftile = blockIdx.x >> 3, chunk = blockIdx.x & 7;  // chunk fastest: L2 dedup
    const int jbase = chunk * JA;
    const int cnt = g_cnt[e];
    if (jbase >= cnt) return;
    const int J  = min(JA, cnt - jbase);
    const int Jp = ((J + 3) >> 2) << 2;

    extern __shared__ __align__(16) float xs[];
    __shared__ int   stok[JA];
    __shared__ float srw [JA];
    const int tid = threadIdx.x;
    if (tid < JA) {
        stok[tid] = (tid < J) ? g_tok[e * NT + jbase + tid] : 0;
        srw [tid] = (tid < J) ? g_rw [e * NT + jbase + tid] : 0.f;
    }
    __syncthreads();

    float4* xs4 = (float4*)xs;
    const float4* x4 = (const float4*)x;
    for (int idx = tid; idx < Jp * 512; idx += 256) {
        const int j = idx >> 9, q = idx & 511;
        xs4[idx] = (j < J) ? __ldg(x4 + (size_t)stok[j] * 512 + q)
                           : make_float4(0.f, 0.f, 0.f, 0.f);
    }
    __syncthreads();

    const int fbase = ftile * 64;
    if (((J + 3) >> 2) == 1)
        stageA_body<4>(w1, v1, (const ulonglong2*)xs, srw, e, fbase, jbase, J);
    else
        stageA_body<8>(w1, v1, (const ulonglong2*)xs, srw, e, fbase, jbase, J);
}

// ---------------------------------------------------------------------------
// Stage B: out[t] += act[e][j] @ w2_e (rw already folded into act).
// Thread owns 8 h (4 u64 accs/j). Per 2-f step: 1 broadcast LDS.64 (8B, free
// broadcast) + 2 pk2 MOVs feed 8 FFMA2 per j -> L1 wf per FFMA2 ~halved vs
// broadcast LDS.128. D=2 ring on the 4 w2 streams. v4 red atomics epilogue.
// ---------------------------------------------------------------------------
template<int JT>
__device__ __forceinline__ void stageB_body(
    const float* __restrict__ w2, float* __restrict__ out,
    const float* sact, const int* stok, int e, int f0, int J)
{
    const int tid = threadIdx.x;                 // 256 threads, h = tid*8
    u64 A0[JT], A1[JT], A2[JT], A3[JT];
#pragma unroll
    for (int j = 0; j < JT; j++) { A0[j] = 0ull; A1[j] = 0ull; A2[j] = 0ull; A3[j] = 0ull; }

    const ulonglong2* wb = (const ulonglong2*)(w2 + ((size_t)e * NF + f0) * NH) + tid * 2;

    ulonglong2 R0[2], R1[2], R2[2], R3[2];       // [slot]: rows 2s (h0..3,h4..7) and 2s+1
#pragma unroll
    for (int s = 0; s < 2; s++) {
        R0[s] = __ldg(wb + (size_t)(2 * s    ) * 512);
        R1[s] = __ldg(wb + (size_t)(2 * s    ) * 512 + 1);
        R2[s] = __ldg(wb + (size_t)(2 * s + 1) * 512);
        R3[s] = __ldg(wb + (size_t)(2 * s + 1) * 512 + 1);
    }

#pragma unroll 2
    for (int s = 0; s < 128; s++) {
        const int sl = s & 1;
#pragma unroll
        for (int j = 0; j < JT; j++) {
            const float2 a2 = *(const float2*)(sact + j * 256 + 2 * s); // LDS.64 bcast
            const u64 dx = pk2(a2.x, a2.x);
            const u64 dy = pk2(a2.y, a2.y);
            fma2(A0[j], R0[sl].x, dx); fma2(A1[j], R0[sl].y, dx);
            fma2(A2[j], R1[sl].x, dx); fma2(A3[j], R1[sl].y, dx);
            fma2(A0[j], R2[sl].x, dy); fma2(A1[j], R2[sl].y, dy);
            fma2(A2[j], R3[sl].x, dy); fma2(A3[j], R3[sl].y, dy);
        }
        if (s < 126) {
            const int t = s + 2;
            R0[sl] = __ldg(wb + (size_t)(2 * t    ) * 512);
            R1[sl] = __ldg(wb + (size_t)(2 * t    ) * 512 + 1);
            R2[sl] = __ldg(wb + (size_t)(2 * t + 1) * 512);
            R3[sl] = __ldg(wb + (size_t)(2 * t + 1) * 512 + 1);
        }
    }

#pragma unroll
    for (int j = 0; j < JT; j++) {
        if (j < J) {
            float a0, a1, a2, a3, a4, a5, a6, a7;
            upk2(A0[j], a0, a1); upk2(A1[j], a2, a3);
            upk2(A2[j], a4, a5); upk2(A3[j], a6, a7);
            float* op = out + (size_t)stok[j] * NH + tid * 8;
            red4(op,     a0, a1, a2, a3);
            red4(op + 4, a4, a5, a6, a7);
        }
    }
}

__global__ void __launch_bounds__(256, 2) stageB_kernel(
    const float* __restrict__ w2, float* __restrict__ out)
{
    const int jc = blockIdx.x, e = blockIdx.y;            // jc fastest: L2 dedup on w2
    const int jbase = jc * JB;
    const int cnt = g_cnt[e];
    if (jbase >= cnt) return;
    const int J  = min(JB, cnt - jbase);
    const int Jp = ((J + 3) >> 2) << 2;
    const int f0 = blockIdx.z * 256;

    extern __shared__ __align__(16) float sact[];         // [JB][256] plain act
    __shared__ int stok[JB];
    const int tid = threadIdx.x;
    if (tid < JB) stok[tid] = (tid < J) ? g_tok[e * NT + jbase + tid] : 0;
    __syncthreads();

    for (int idx = tid; idx < Jp * 256; idx += 256) {
        const int j = idx >> 8, q = idx & 255;
        sact[idx] = (j < J)
            ? g_act[((size_t)(e * NT + jbase + j)) * NF + f0 + q] : 0.f;
    }
    __syncthreads();

    if (((J + 3) >> 2) == 1)
        stageB_body<4>(w2, out, sact, stok, e, f0, J);
    else
        stageB_body<8>(w2, out, sact, stok, e, f0, J);
}

// ---------------------------------------------------------------------------
extern "C" void kernel_launch(void* const* d_in, const int* in_sizes, int n_in,
                              void* d_out, int out_size)
{
    const float* x    = (const float*)d_in[0];
    const float* topw = (const float*)d_in[2];
    const int*   tope = (const int*)  d_in[3];
    const float* w1   = (const float*)d_in[4];
    const float* v1   = (const float*)d_in[5];
    const float* w2   = (const float*)d_in[6];
    float* out = (float*)d_out;

    cudaFuncSetAttribute(stageA_kernel, cudaFuncAttributeMaxDynamicSharedMemorySize, JA * NH * 4);
    cudaFuncSetAttribute(stageB_kernel, cudaFuncAttributeMaxDynamicSharedMemorySize, JB * 256 * 4);

    setup_kernel<<<64, 256>>>(tope, topw, out);
    stageA_kernel<<<dim3(512, NE), 256, JA * NH * 4>>>(x, w1, v1);
    stageB_kernel<<<dim3(8, NE, 16), 256, JB * 256 * 4>>>(w2, out);
}